// round 14
// baseline (speedup 1.0000x reference)
#include <cuda_runtime.h>
#include <float.h>
#include <stdint.h>

#define MAXN 12000
#define KNN  20
#define NCHUNK 4
#define CAP  8

typedef unsigned long long ull;

// ---------------- scratch (static device globals; no runtime allocation) ---
__device__ int   g_idx[MAXN * KNN];
__device__ float g_pd[(size_t)NCHUNK * MAXN * KNN];
__device__ int   g_pi[(size_t)NCHUNK * MAXN * KNN];
__device__ float g_X0[MAXN * 4];
__device__ float g_Xt[(size_t)64 * MAXN];
__device__ float g_X14[MAXN * 256];
__device__ float g_Y5[(size_t)MAXN * 1024];
__device__ float g_F[MAXN * 256];

// ---------------- f32x2 packed helpers -------------------------------------
__device__ __forceinline__ ull pack_dup(float x) {
    ull r;
    asm("mov.b64 %0, {%1, %1};" : "=l"(r) : "f"(x));
    return r;
}
__device__ __forceinline__ ull add2(ull a, ull b) {
    ull r;
    asm("add.rn.f32x2 %0, %1, %2;" : "=l"(r) : "l"(a), "l"(b));
    return r;
}
__device__ __forceinline__ ull fma2(ull a, ull b, ull c) {
    ull r;
    asm("fma.rn.f32x2 %0, %1, %2, %3;" : "=l"(r) : "l"(a), "l"(b), "l"(c));
    return r;
}
__device__ __forceinline__ void unpack2(ull v, float& lo, float& hi) {
    asm("mov.b64 {%0, %1}, %2;" : "=f"(lo), "=f"(hi) : "l"(v));
}

// ---------------- fused kNN: warp-owned rows, 3 blocks/SM ------------------
// Warp w owns rows 8w..8w+7 of the 64-row block; lane owns 4 cols of the
// 128-col tile. Distance chain bit-identical: ascending-k d = add2(a, -b);
// acc = fma2(d, d, acc). Lists seeded with exact distances of the chunk's
// first 20 columns; main loop skips those columns. Running top-20 per row,
// lexicographic (d, idx); output order arbitrary (max-pool is invariant).
#define FTM 64
#define FTN 128

template <int KD>
__global__ void __launch_bounds__(256, 3) fused_knn(
    const float* __restrict__ Xt,
    float* __restrict__ pd, int* __restrict__ pi, int N)
{
    extern __shared__ __align__(16) char smraw[];
    float* As    = (float*)smraw;                 // [KD][64]
    float* Bs    = As + KD * 64;                  // [KD][132], negated
    float* listD = Bs + KD * 132;                 // [64][20]
    int*   listI = (int*)(listD + 64 * KNN);      // [64][20]
    float* wdv_  = (float*)(listI + 64 * KNN);    // [64] worst d
    int*   wiv_  = (int*)(wdv_ + 64);             // [64] worst idx
    float* bufD  = (float*)(wiv_ + 64);           // [64][CAP]
    int*   bufI  = (int*)(bufD + 64 * CAP);       // [64][CAP]
    int*   cnt   = bufI + 64 * CAP;               // [64]

    int tid  = threadIdx.x;
    int w    = tid >> 5;
    int ln   = tid & 31;
    int bm   = blockIdx.x * FTM;
    int row0 = w * 8;

    int chunk = blockIdx.y;
    int cs = (N + NCHUNK - 1) / NCHUNK;
    int n0 = chunk * cs;
    int n1 = (n0 + cs < N) ? (n0 + cs) : N;

    for (int e = tid; e < KD * 64; e += 256) {
        int k = e >> 6, m = e & 63;
        int gm = bm + m;
        As[k * 64 + m] = (gm < N) ? Xt[(size_t)k * N + gm] : 0.f;
    }
    if (tid < 64) cnt[tid] = 0;
    __syncthreads();

    int mycol = ln * 4;
    int ntiles = (n1 - n0 + FTN - 1) / FTN;

    for (int t = 0; t < ntiles; t++) {
        int bn = n0 + t * FTN;
        // B panel (negated), float4 coalesced
        for (int e = tid; e < KD * 32; e += 256) {
            int k = e >> 5;
            int nn = (e & 31) * 4;
            int gn = bn + nn;
            float4 v = make_float4(0.f, 0.f, 0.f, 0.f);
            const float* src = Xt + (size_t)k * N;
            if (gn + 3 < n1) v = *reinterpret_cast<const float4*>(&src[gn]);
            else {
                if (gn + 0 < n1) v.x = src[gn + 0];
                if (gn + 1 < n1) v.y = src[gn + 1];
                if (gn + 2 < n1) v.z = src[gn + 2];
            }
            float4 nv = make_float4(-v.x, -v.y, -v.z, -v.w);
            *reinterpret_cast<float4*>(&Bs[k * 132 + nn]) = nv;
        }
        __syncthreads();

        if (t == 0) {
            // seed lists with exact distances to cols n0..n0+19 (in tile 0;
            // Bs holds -b so d = a + Bs is the identical rounded op)
            if (ln < KNN) {
                for (int r = 0; r < 8; r++) {
                    int row = row0 + r;
                    float acc = 0.f;
                    for (int k = 0; k < KD; k++) {
                        float d = __fadd_rn(As[k * 64 + row], Bs[k * 132 + ln]);
                        acc = fmaf(d, d, acc);
                    }
                    listD[row * KNN + ln] = acc;
                    listI[row * KNN + ln] = n0 + ln;
                }
            }
            __syncwarp();
            if (ln < 8) {
                int row = row0 + ln;
                float wv = listD[row * KNN]; int wj = listI[row * KNN];
                for (int q = 1; q < KNN; q++) {
                    float qd = listD[row * KNN + q]; int qj = listI[row * KNN + q];
                    if (qd > wv || (qd == wv && qj > wj)) { wv = qd; wj = qj; }
                }
                wdv_[row] = wv; wiv_[row] = wj;
            }
            __syncwarp();
        }

        // compute 8 rows x 4 cols per lane; A reads are warp-broadcast
        ull acc2[8][2];
#pragma unroll
        for (int r = 0; r < 8; r++) { acc2[r][0] = 0ULL; acc2[r][1] = 0ULL; }

#pragma unroll 16
        for (int kk = 0; kk < KD; kk++) {
            float4 a0 = *reinterpret_cast<const float4*>(&As[kk * 64 + row0]);
            float4 a1 = *reinterpret_cast<const float4*>(&As[kk * 64 + row0 + 4]);
            ulonglong2 b = *reinterpret_cast<const ulonglong2*>(&Bs[kk * 132 + mycol]);
            float ar[8] = {a0.x, a0.y, a0.z, a0.w, a1.x, a1.y, a1.z, a1.w};
#pragma unroll
            for (int r = 0; r < 8; r++) {
                ull a2 = pack_dup(ar[r]);
                ull d0 = add2(a2, b.x); acc2[r][0] = fma2(d0, d0, acc2[r][0]);
                ull d1 = add2(a2, b.y); acc2[r][1] = fma2(d1, d1, acc2[r][1]);
            }
        }

        // selection: detect hits vs current per-row worst, ballot fast-path
        int jb = bn + mycol;
        int jlo = n0 + KNN;      // seeds excluded
        unsigned pend = 0u;
#pragma unroll
        for (int r = 0; r < 8; r++) {
            int row = row0 + r;
            float wv = wdv_[row]; int wj = wiv_[row];
            float c0, c1, c2, c3;
            unpack2(acc2[r][0], c0, c1);
            unpack2(acc2[r][1], c2, c3);
            if (jb + 0 < n1 && jb + 0 >= jlo && (c0 < wv || (c0 == wv && jb + 0 < wj))) pend |= 1u << (r * 4 + 0);
            if (jb + 1 < n1 && jb + 1 >= jlo && (c1 < wv || (c1 == wv && jb + 1 < wj))) pend |= 1u << (r * 4 + 1);
            if (jb + 2 < n1 && jb + 2 >= jlo && (c2 < wv || (c2 == wv && jb + 2 < wj))) pend |= 1u << (r * 4 + 2);
            if (jb + 3 < n1 && jb + 3 >= jlo && (c3 < wv || (c3 == wv && jb + 3 < wj))) pend |= 1u << (r * 4 + 3);
        }
        while (__ballot_sync(0xffffffffu, pend != 0u)) {
#pragma unroll
            for (int r = 0; r < 8; r++) {
#pragma unroll
                for (int e = 0; e < 4; e++) {
                    unsigned bit = 1u << (r * 4 + e);
                    if (pend & bit) {
                        int row = row0 + r;
                        int pos = atomicAdd(&cnt[row], 1);
                        if (pos < CAP) {
                            float x0, x1;
                            unpack2(acc2[r][e >> 1], x0, x1);
                            bufD[row * CAP + pos] = (e & 1) ? x1 : x0;
                            bufI[row * CAP + pos] = jb + e;
                            pend &= ~bit;
                        }
                    }
                }
            }
            __syncwarp();
            if (ln < 8) {
                int row = row0 + ln;
                int c = cnt[row]; if (c > CAP) c = CAP;
                if (c > 0) {
                    float wv = wdv_[row]; int wj = wiv_[row];
                    for (int u = 0; u < c; u++) {
                        float d = bufD[row * CAP + u];
                        int   j = bufI[row * CAP + u];
                        if (d < wv || (d == wv && j < wj)) {
                            // worst slot = slot holding (wv, wj)
                            int ws = 0;
                            for (int q = 0; q < KNN; q++)
                                if (listD[row * KNN + q] == wv &&
                                    listI[row * KNN + q] == wj) ws = q;
                            listD[row * KNN + ws] = d;
                            listI[row * KNN + ws] = j;
                            wv = listD[row * KNN]; wj = listI[row * KNN];
                            for (int q = 1; q < KNN; q++) {
                                float qd = listD[row * KNN + q];
                                int   qj = listI[row * KNN + q];
                                if (qd > wv || (qd == wv && qj > wj)) { wv = qd; wj = qj; }
                            }
                        }
                    }
                    wdv_[row] = wv; wiv_[row] = wj;
                    cnt[row] = 0;
                }
            }
            __syncwarp();
        }
        __syncthreads();   // compute+selection done before Bs overwrite
    }

    // write chunk-partial lists
    for (int r = 0; r < 8; r++) {
        int row = row0 + r;
        int grow = bm + row;
        if (grow < N && ln < KNN) {
            size_t base = ((size_t)chunk * MAXN + grow) * KNN;
            pd[base + ln] = listD[row * KNN + ln];
            pi[base + ln] = listI[row * KNN + ln];
        }
    }
}

// ---------------- merge chunk-partial top-20 lists -------------------------
__global__ void knn_merge_kernel(const float* __restrict__ pd,
                                 const int* __restrict__ pi,
                                 int* __restrict__ out, int N)
{
    int m = blockIdx.x * blockDim.x + threadIdx.x;
    if (m >= N) return;
    float ld[KNN]; int li[KNN];
    size_t b0 = (size_t)m * KNN;
#pragma unroll
    for (int s = 0; s < KNN; s++) { ld[s] = pd[b0 + s]; li[s] = pi[b0 + s]; }
    float wd = ld[0]; int wi = li[0]; int ws = 0;
#pragma unroll
    for (int q = 1; q < KNN; q++) {
        if (ld[q] > wd || (ld[q] == wd && li[q] > wi)) { wd = ld[q]; wi = li[q]; ws = q; }
    }
    for (int c = 1; c < NCHUNK; c++) {
        size_t bc = ((size_t)c * MAXN + m) * KNN;
        for (int s = 0; s < KNN; s++) {
            float d = pd[bc + s];
            int   j = pi[bc + s];
            if ((d < wd) || (d == wd && j < wi)) {
                ld[ws] = d; li[ws] = j;
                wd = ld[0]; wi = li[0]; ws = 0;
#pragma unroll
                for (int q = 1; q < KNN; q++) {
                    if (ld[q] > wd || (ld[q] == wd && li[q] > wi)) {
                        wd = ld[q]; wi = li[q]; ws = q;
                    }
                }
            }
        }
    }
#pragma unroll
    for (int s = 0; s < KNN; s++) out[m * KNN + s] = li[s];
}

// ---------------- generic NT SGEMM (f32x2 packed, exact ascending chains) --
#define TBM 64
#define TBN 64
#define TBK 16

#define EPI_AFF        1
#define EPI_AFF_LRELU  2

template <int EPI>
__global__ void __launch_bounds__(256) sgemm_nt(
    const float* __restrict__ A, int lda,
    const float* __restrict__ B, int ldb,
    float* __restrict__ C, int ldc,
    int M, int N, int Kd,
    const float* __restrict__ gv, const float* __restrict__ bv)
{
    __shared__ __align__(16) float As[TBK][TBM];
    __shared__ __align__(16) float Bs[TBK][TBN];

    int tid = threadIdx.x;
    int bm = blockIdx.y * TBM;
    int bn = blockIdx.x * TBN;
    int tx = tid & 15;
    int ty = tid >> 4;
    int lr = tid >> 2;
    int lk = (tid & 3) * 4;

    ull acc2[4][2];
#pragma unroll
    for (int i = 0; i < 4; i++) { acc2[i][0] = 0ULL; acc2[i][1] = 0ULL; }

    int am  = bm + lr;
    int bnr = bn + lr;

    for (int k0 = 0; k0 < Kd; k0 += TBK) {
#pragma unroll
        for (int i = 0; i < 4; i++) {
            int k = k0 + lk + i;
            As[lk + i][lr] = (am  < M && k < Kd) ? A[(size_t)am  * lda + k] : 0.f;
            Bs[lk + i][lr] = (bnr < N && k < Kd) ? B[(size_t)bnr * ldb + k] : 0.f;
        }
        __syncthreads();
#pragma unroll
        for (int kk = 0; kk < TBK; kk++) {
            float4 a4 = *reinterpret_cast<const float4*>(&As[kk][ty * 4]);
            ulonglong2 bb = *reinterpret_cast<const ulonglong2*>(&Bs[kk][tx * 4]);
            float ar[4] = { a4.x, a4.y, a4.z, a4.w };
#pragma unroll
            for (int i = 0; i < 4; i++) {
                ull a2 = pack_dup(ar[i]);
                acc2[i][0] = fma2(a2, bb.x, acc2[i][0]);
                acc2[i][1] = fma2(a2, bb.y, acc2[i][1]);
            }
        }
        __syncthreads();
    }

#pragma unroll
    for (int i = 0; i < 4; i++) {
        int m = bm + ty * 4 + i;
        if (m >= M) continue;
        float c[4];
        unpack2(acc2[i][0], c[0], c[1]);
        unpack2(acc2[i][1], c[2], c[3]);
#pragma unroll
        for (int j = 0; j < 4; j++) {
            int n = bn + tx * 4 + j;
            if (n >= N) continue;
            float v = c[j];
            float gg = gv ? gv[n] : 1.f;
            float bb = bv ? bv[n] : 0.f;
            v = __fadd_rn(__fmul_rn(v, gg), bb);
            if (EPI == EPI_AFF_LRELU)
                v = (v >= 0.f) ? v : __fmul_rn(0.2f, v);
            C[(size_t)m * ldc + n] = v;
        }
    }
}

// ---------------- helpers ---------------------------------------------------
__global__ void concat_kernel(const float* __restrict__ pts,
                              const float* __restrict__ feat,
                              float* __restrict__ X0,
                              float* __restrict__ Xt, int N)
{
    int n = blockIdx.x * blockDim.x + threadIdx.x;
    if (n >= N) return;
    float x = pts[n * 3 + 0];
    float y = pts[n * 3 + 1];
    float z = pts[n * 3 + 2];
    float f = feat[n];
    X0[n * 4 + 0] = x;
    X0[n * 4 + 1] = y;
    X0[n * 4 + 2] = z;
    X0[n * 4 + 3] = f;
    Xt[(size_t)0 * N + n] = x;
    Xt[(size_t)1 * N + n] = y;
    Xt[(size_t)2 * N + n] = z;
    Xt[(size_t)3 * N + n] = f;
}

// ---------------- fused edge conv (exact fp32) + transposed output ---------
template <int C>
__global__ void __launch_bounds__(256) edge_conv_kernel(
    const float* __restrict__ X, int lda,
    const float* __restrict__ w,      // [64, 2C]
    const int* __restrict__ idx,
    const float* __restrict__ g, const float* __restrict__ b,
    float* __restrict__ out, int colofs,
    float* __restrict__ Xt, int N)
{
    __shared__ float ws[2 * C][64];
    __shared__ float xs[4][C];
    __shared__ float ds[4][C];

    int tid = threadIdx.x;
    int o = tid & 63;
    int r = tid >> 6;
    int n = blockIdx.x * 4 + r;
    bool active = (n < N);

    for (int e = tid; e < 2 * C * 64; e += 256) {
        int oo = e / (2 * C), cc = e % (2 * C);
        ws[cc][oo] = w[oo * 2 * C + cc];
    }
    if (active) {
        for (int c = o; c < C; c += 64)
            xs[r][c] = X[(size_t)n * lda + c];
    }
    __syncthreads();

    float gg = active ? g[o] : 0.f;
    float bb = active ? b[o] : 0.f;
    float m = -FLT_MAX;
    const int* row = idx + (size_t)(active ? n : 0) * KNN;

    for (int k = 0; k < KNN; k++) {
        int j = active ? row[k] : 0;
        if (active && o < C)
            ds[r][o] = __fsub_rn(X[(size_t)j * lda + o], xs[r][o]);
        __syncthreads();
        if (active) {
            float y = 0.f;
#pragma unroll
            for (int c = 0; c < C; c++)
                y = fmaf(ds[r][c], ws[c][o], y);
#pragma unroll
            for (int c = 0; c < C; c++)
                y = fmaf(xs[r][c], ws[C + c][o], y);
            float z = __fadd_rn(__fmul_rn(y, gg), bb);
            z = (z >= 0.f) ? z : __fmul_rn(0.2f, z);
            m = fmaxf(m, z);
        }
        __syncthreads();
    }
    if (active) {
        out[(size_t)n * 256 + colofs + o] = m;
        if (Xt) Xt[(size_t)o * N + n] = m;
    }
}

// ---------------- launch ----------------------------------------------------
static inline int fused_smem_bytes(int KD) {
    return KD * 64 * 4 + KD * 132 * 4 + 64 * KNN * 4 * 2
         + 64 * 4 * 2 + 64 * CAP * 4 * 2 + 64 * 4;
}

extern "C" void kernel_launch(void* const* d_in, const int* in_sizes, int n_in,
                              void* d_out, int out_size)
{
    const float* pts   = (const float*)d_in[0];
    const float* feats = (const float*)d_in[1];
    const float* W[4]  = { (const float*)d_in[2], (const float*)d_in[5],
                           (const float*)d_in[8], (const float*)d_in[11] };
    const float* G[4]  = { (const float*)d_in[3], (const float*)d_in[6],
                           (const float*)d_in[9], (const float*)d_in[12] };
    const float* Bv[4] = { (const float*)d_in[4], (const float*)d_in[7],
                           (const float*)d_in[10], (const float*)d_in[13] };
    const float* w5 = (const float*)d_in[14];
    const float* g5 = (const float*)d_in[15];
    const float* b5 = (const float*)d_in[16];
    const float* wf = (const float*)d_in[17];
    const float* go = (const float*)d_in[18];
    const float* bo = (const float*)d_in[19];
    const float* wh = (const float*)d_in[20];
    const float* bh = (const float*)d_in[21];
    float* outp = (float*)d_out;

    int N = in_sizes[0] / 3;   // 12000

    float *pX0, *pXt, *pX14, *pY5, *pF, *ppd;
    int *pidx, *ppi;
    cudaGetSymbolAddress((void**)&pidx, g_idx);
    cudaGetSymbolAddress((void**)&ppd,  g_pd);
    cudaGetSymbolAddress((void**)&ppi,  g_pi);
    cudaGetSymbolAddress((void**)&pX0,  g_X0);
    cudaGetSymbolAddress((void**)&pXt,  g_Xt);
    cudaGetSymbolAddress((void**)&pX14, g_X14);
    cudaGetSymbolAddress((void**)&pY5,  g_Y5);
    cudaGetSymbolAddress((void**)&pF,   g_F);

    static bool attr_done = false;
    if (!attr_done) {
        cudaFuncSetAttribute(fused_knn<4>,
            cudaFuncAttributeMaxDynamicSharedMemorySize, fused_smem_bytes(4));
        cudaFuncSetAttribute(fused_knn<64>,
            cudaFuncAttributeMaxDynamicSharedMemorySize, fused_smem_bytes(64));
        attr_done = true;
    }

    int nb256 = (N + 255) / 256;
    int nb4   = (N + 3) / 4;
    int nbM   = (N + FTM - 1) / FTM;
    dim3 gKnn(nbM, NCHUNK);

    // L1
    concat_kernel<<<nb256, 256>>>(pts, feats, pX0, pXt, N);
    fused_knn<4><<<gKnn, 256, fused_smem_bytes(4)>>>(pXt, ppd, ppi, N);
    knn_merge_kernel<<<nb256, 256>>>(ppd, ppi, pidx, N);
    edge_conv_kernel<4><<<nb4, 256>>>(pX0, 4, W[0], pidx, G[0], Bv[0],
                                      pX14, 0, pXt, N);

    // L2..L4
    for (int blk = 1; blk < 4; blk++) {
        const float* Xin = pX14 + (blk - 1) * 64;
        fused_knn<64><<<gKnn, 256, fused_smem_bytes(64)>>>(pXt, ppd, ppi, N);
        knn_merge_kernel<<<nb256, 256>>>(ppd, ppi, pidx, N);
        edge_conv_kernel<64><<<nb4, 256>>>(Xin, 256, W[blk], pidx,
                                           G[blk], Bv[blk], pX14, blk * 64,
                                           (blk < 3) ? pXt : nullptr, N);
    }

    // conv5 / feat / head
    sgemm_nt<EPI_AFF_LRELU><<<dim3((1024 + 63) / 64, (N + 63) / 64), 256>>>(
        pX14, 256, w5, 256, pY5, 1024, N, 1024, 256, g5, b5);
    sgemm_nt<EPI_AFF><<<dim3((256 + 63) / 64, (N + 63) / 64), 256>>>(
        pY5, 1024, wf, 1024, pF, 256, N, 256, 1024, go, bo);
    sgemm_nt<EPI_AFF><<<dim3(1, (N + 63) / 64), 256>>>(
        pF, 256, wh, 256, outp, 20, N, 20, 256, nullptr, bh);
}

// round 16
// speedup vs baseline: 1.2127x; 1.2127x over previous
#include <cuda_runtime.h>
#include <float.h>
#include <stdint.h>

#define MAXN 12000
#define KNN  20
#define NCHUNK 4
#define CAPB 22

typedef unsigned long long ull;

// ---------------- scratch (static device globals; no runtime allocation) ---
__device__ int   g_idx[MAXN * KNN];
__device__ float g_pd[(size_t)NCHUNK * MAXN * KNN];
__device__ int   g_pi[(size_t)NCHUNK * MAXN * KNN];
__device__ float g_X0[MAXN * 4];
__device__ float g_Xt[(size_t)64 * MAXN];
__device__ float g_X14[MAXN * 256];
__device__ float g_Y5[(size_t)MAXN * 1024];
__device__ float g_F[MAXN * 256];

// ---------------- f32x2 packed helpers -------------------------------------
__device__ __forceinline__ ull pack_dup(float x) {
    ull r;
    asm("mov.b64 %0, {%1, %1};" : "=l"(r) : "f"(x));
    return r;
}
__device__ __forceinline__ ull add2(ull a, ull b) {
    ull r;
    asm("add.rn.f32x2 %0, %1, %2;" : "=l"(r) : "l"(a), "l"(b));
    return r;
}
__device__ __forceinline__ ull fma2(ull a, ull b, ull c) {
    ull r;
    asm("fma.rn.f32x2 %0, %1, %2, %3;" : "=l"(r) : "l"(a), "l"(b), "l"(c));
    return r;
}
__device__ __forceinline__ void unpack2(ull v, float& lo, float& hi) {
    asm("mov.b64 {%0, %1}, %2;" : "=f"(lo), "=f"(hi) : "l"(v));
}

// ---------------- fused kNN over a column chunk (3 blocks/SM) --------------
// Structure identical to the proven R12 kernel; only the insert buffer is
// capped (CAPB) with a pend-mask retry loop, shrinking smem 95.5->74.0 KB so
// 3 blocks co-reside per SM. Distance chain bit-identical; selected set
// identical (retries re-test against the updated worst -> same final top-20).
#define FTM 64
#define FTN 128

template <int KD>
__global__ void __launch_bounds__(256, 3) fused_knn(
    const float* __restrict__ Xt,
    float* __restrict__ pd, int* __restrict__ pi, int N)
{
    extern __shared__ __align__(16) char smraw[];
    float* As    = (float*)smraw;                 // [KD][68]
    float* Bs    = As + KD * 68;                  // [KD][132], negated
    float* listD = Bs + KD * 132;                 // [64][20]
    int*   listI = (int*)(listD + 64 * KNN);      // [64][20]
    float* bufD  = (float*)(listI + 64 * KNN);    // [64][CAPB]
    int*   bufI  = (int*)(bufD + 64 * CAPB);      // [64][CAPB]
    float* swd   = (float*)(bufI + 64 * CAPB);    // [64] worst d
    int*   swi   = (int*)(swd + 64);              // [64] worst idx
    int*   ssz   = swi + 64;                      // [64] list size
    int*   sws   = ssz + 64;                      // [64] worst slot
    int*   cnt   = sws + 64;                      // [64] buffer count

    int tid = threadIdx.x;
    int tx = tid & 15;
    int ty = tid >> 4;
    int bm = blockIdx.x * FTM;

    int chunk = blockIdx.y;
    int cs = (N + NCHUNK - 1) / NCHUNK;
    int n0 = chunk * cs;
    int n1 = (n0 + cs < N) ? (n0 + cs) : N;

    if (tid < 64) {
        swd[tid] = FLT_MAX; swi[tid] = 0x7FFFFFFF;
        ssz[tid] = 0; sws[tid] = 0; cnt[tid] = 0;
#pragma unroll
        for (int s = 0; s < KNN; s++) {
            listD[tid * KNN + s] = FLT_MAX;
            listI[tid * KNN + s] = 0x7FFFFFFF;
        }
    }

    // A panel: once per block
    for (int e = tid; e < KD * 64; e += 256) {
        int k = e >> 6, mm = e & 63;
        int gm = bm + mm;
        As[k * 68 + mm] = (gm < N) ? Xt[(size_t)k * N + gm] : 0.f;
    }
    __syncthreads();

    int ntiles = (n1 - n0 + FTN - 1) / FTN;
    for (int t = 0; t < ntiles; t++) {
        int bn = n0 + t * FTN;
        // B panel (negated), float4 coalesced
        for (int e = tid; e < KD * 32; e += 256) {
            int k = e >> 5;
            int nn = (e & 31) * 4;
            int gn = bn + nn;
            float4 v = make_float4(0.f, 0.f, 0.f, 0.f);
            const float* src = Xt + (size_t)k * N;
            if (gn + 3 < n1) v = *reinterpret_cast<const float4*>(&src[gn]);
            else {
                if (gn + 0 < n1) v.x = src[gn + 0];
                if (gn + 1 < n1) v.y = src[gn + 1];
                if (gn + 2 < n1) v.z = src[gn + 2];
            }
            float4 nv = make_float4(-v.x, -v.y, -v.z, -v.w);
            *reinterpret_cast<float4*>(&Bs[k * 132 + nn]) = nv;
        }
        __syncthreads();

        ull acc2[4][4];
#pragma unroll
        for (int i = 0; i < 4; i++)
#pragma unroll
            for (int j = 0; j < 4; j++) acc2[i][j] = 0ULL;

#pragma unroll
        for (int kk = 0; kk < KD; kk++) {
            float4 a4 = *reinterpret_cast<const float4*>(&As[kk * 68 + ty * 4]);
            ulonglong2 b0 = *reinterpret_cast<const ulonglong2*>(&Bs[kk * 132 + tx * 4]);
            ulonglong2 b1 = *reinterpret_cast<const ulonglong2*>(&Bs[kk * 132 + 64 + tx * 4]);
            float ar[4] = { a4.x, a4.y, a4.z, a4.w };
#pragma unroll
            for (int i = 0; i < 4; i++) {
                ull a2 = pack_dup(ar[i]);
                ull d0 = add2(a2, b0.x); acc2[i][0] = fma2(d0, d0, acc2[i][0]);
                ull d1 = add2(a2, b0.y); acc2[i][1] = fma2(d1, d1, acc2[i][1]);
                ull d2 = add2(a2, b1.x); acc2[i][2] = fma2(d2, d2, acc2[i][2]);
                ull d3 = add2(a2, b1.y); acc2[i][3] = fma2(d3, d3, acc2[i][3]);
            }
        }

        // selection: two 64-col halves; capped buffer + pend-mask retry
#pragma unroll
        for (int cq = 0; cq < 2; cq++) {
            unsigned pend = 0u;   // bit = i*4 + pair*2 + e
#pragma unroll
            for (int i = 0; i < 4; i++) {
                int r = ty * 4 + i;
                float wdv = swd[r];
                int   wiv = swi[r];
#pragma unroll
                for (int pair = 0; pair < 2; pair++) {
                    float d0, d1;
                    unpack2(acc2[i][cq * 2 + pair], d0, d1);
                    int j0 = bn + cq * 64 + tx * 4 + pair * 2;
#pragma unroll
                    for (int e = 0; e < 2; e++) {
                        float d = (e == 0) ? d0 : d1;
                        int   j = j0 + e;
                        if (j < n1 && ((d < wdv) || (d == wdv && j < wiv))) {
                            int pos = atomicAdd(&cnt[r], 1);
                            if (pos < CAPB) {
                                bufD[r * CAPB + pos] = d;
                                bufI[r * CAPB + pos] = j;
                            } else {
                                pend |= 1u << (i * 4 + pair * 2 + e);
                            }
                        }
                    }
                }
            }
            int more = __syncthreads_or(pend != 0u ? 1 : 0);
            for (;;) {
                if (tid < 64) {
                    int r = tid;
                    int c = cnt[r]; if (c > CAPB) c = CAPB;
                    if (c > 0) {
                        int sz = ssz[r];
                        float wdv = swd[r]; int wiv = swi[r]; int wsv = sws[r];
                        for (int u = 0; u < c; u++) {
                            float d = bufD[r * CAPB + u];
                            int   j = bufI[r * CAPB + u];
                            if (sz < KNN) {
                                listD[r * KNN + sz] = d;
                                listI[r * KNN + sz] = j;
                                sz++;
                                if (sz == KNN) {
                                    wdv = listD[r * KNN]; wiv = listI[r * KNN]; wsv = 0;
                                    for (int q = 1; q < KNN; q++) {
                                        float qd = listD[r * KNN + q];
                                        int   qi = listI[r * KNN + q];
                                        if (qd > wdv || (qd == wdv && qi > wiv)) {
                                            wdv = qd; wiv = qi; wsv = q;
                                        }
                                    }
                                }
                            } else if ((d < wdv) || (d == wdv && j < wiv)) {
                                listD[r * KNN + wsv] = d;
                                listI[r * KNN + wsv] = j;
                                wdv = listD[r * KNN]; wiv = listI[r * KNN]; wsv = 0;
                                for (int q = 1; q < KNN; q++) {
                                    float qd = listD[r * KNN + q];
                                    int   qi = listI[r * KNN + q];
                                    if (qd > wdv || (qd == wdv && qi > wiv)) {
                                        wdv = qd; wiv = qi; wsv = q;
                                    }
                                }
                            }
                        }
                        ssz[r] = sz;
                        if (sz == KNN) { swd[r] = wdv; swi[r] = wiv; sws[r] = wsv; }
                        cnt[r] = 0;
                    }
                }
                __syncthreads();
                if (!more) break;
                // retry pending candidates against the updated worst
                unsigned p = pend; pend = 0u;
                if (p) {
                    for (int bit = 0; bit < 16; bit++) {
                        if (!(p & (1u << bit))) continue;
                        int i = bit >> 2, pair = (bit >> 1) & 1, e = bit & 1;
                        int r = ty * 4 + i;
                        float x0, x1;
                        unpack2(acc2[i][cq * 2 + pair], x0, x1);
                        float d = e ? x1 : x0;
                        int j = bn + cq * 64 + tx * 4 + pair * 2 + e;
                        float wdv = swd[r]; int wiv = swi[r];
                        if ((d < wdv) || (d == wdv && j < wiv)) {
                            int pos = atomicAdd(&cnt[r], 1);
                            if (pos < CAPB) {
                                bufD[r * CAPB + pos] = d;
                                bufI[r * CAPB + pos] = j;
                            } else {
                                pend |= 1u << bit;
                            }
                        }
                    }
                }
                more = __syncthreads_or(pend != 0u ? 1 : 0);
            }
        }
    }

    if (tid < 64) {
        int m = bm + tid;
        if (m < N) {
            size_t base = ((size_t)chunk * MAXN + m) * KNN;
#pragma unroll
            for (int s = 0; s < KNN; s++) {
                pd[base + s] = listD[tid * KNN + s];
                pi[base + s] = listI[tid * KNN + s];
            }
        }
    }
}

// ---------------- merge chunk-partial top-20 lists -------------------------
__global__ void knn_merge_kernel(const float* __restrict__ pd,
                                 const int* __restrict__ pi,
                                 int* __restrict__ out, int N)
{
    int m = blockIdx.x * blockDim.x + threadIdx.x;
    if (m >= N) return;
    float ld[KNN]; int li[KNN];
    size_t b0 = (size_t)m * KNN;
#pragma unroll
    for (int s = 0; s < KNN; s++) { ld[s] = pd[b0 + s]; li[s] = pi[b0 + s]; }
    float wd = ld[0]; int wi = li[0]; int ws = 0;
#pragma unroll
    for (int q = 1; q < KNN; q++) {
        if (ld[q] > wd || (ld[q] == wd && li[q] > wi)) { wd = ld[q]; wi = li[q]; ws = q; }
    }
    for (int c = 1; c < NCHUNK; c++) {
        size_t bc = ((size_t)c * MAXN + m) * KNN;
        for (int s = 0; s < KNN; s++) {
            float d = pd[bc + s];
            int   j = pi[bc + s];
            if ((d < wd) || (d == wd && j < wi)) {
                ld[ws] = d; li[ws] = j;
                wd = ld[0]; wi = li[0]; ws = 0;
#pragma unroll
                for (int q = 1; q < KNN; q++) {
                    if (ld[q] > wd || (ld[q] == wd && li[q] > wi)) {
                        wd = ld[q]; wi = li[q]; ws = q;
                    }
                }
            }
        }
    }
#pragma unroll
    for (int s = 0; s < KNN; s++) out[m * KNN + s] = li[s];
}

// ---------------- generic NT SGEMM (f32x2 packed, exact ascending chains) --
#define TBM 64
#define TBN 64
#define TBK 16

#define EPI_AFF        1
#define EPI_AFF_LRELU  2

template <int EPI>
__global__ void __launch_bounds__(256) sgemm_nt(
    const float* __restrict__ A, int lda,
    const float* __restrict__ B, int ldb,
    float* __restrict__ C, int ldc,
    int M, int N, int Kd,
    const float* __restrict__ gv, const float* __restrict__ bv)
{
    __shared__ __align__(16) float As[TBK][TBM];
    __shared__ __align__(16) float Bs[TBK][TBN];

    int tid = threadIdx.x;
    int bm = blockIdx.y * TBM;
    int bn = blockIdx.x * TBN;
    int tx = tid & 15;
    int ty = tid >> 4;
    int lr = tid >> 2;
    int lk = (tid & 3) * 4;

    ull acc2[4][2];
#pragma unroll
    for (int i = 0; i < 4; i++) { acc2[i][0] = 0ULL; acc2[i][1] = 0ULL; }

    int am  = bm + lr;
    int bnr = bn + lr;

    for (int k0 = 0; k0 < Kd; k0 += TBK) {
#pragma unroll
        for (int i = 0; i < 4; i++) {
            int k = k0 + lk + i;
            As[lk + i][lr] = (am  < M && k < Kd) ? A[(size_t)am  * lda + k] : 0.f;
            Bs[lk + i][lr] = (bnr < N && k < Kd) ? B[(size_t)bnr * ldb + k] : 0.f;
        }
        __syncthreads();
#pragma unroll
        for (int kk = 0; kk < TBK; kk++) {
            float4 a4 = *reinterpret_cast<const float4*>(&As[kk][ty * 4]);
            ulonglong2 bb = *reinterpret_cast<const ulonglong2*>(&Bs[kk][tx * 4]);
            float ar[4] = { a4.x, a4.y, a4.z, a4.w };
#pragma unroll
            for (int i = 0; i < 4; i++) {
                ull a2 = pack_dup(ar[i]);
                acc2[i][0] = fma2(a2, bb.x, acc2[i][0]);
                acc2[i][1] = fma2(a2, bb.y, acc2[i][1]);
            }
        }
        __syncthreads();
    }

#pragma unroll
    for (int i = 0; i < 4; i++) {
        int m = bm + ty * 4 + i;
        if (m >= M) continue;
        float c[4];
        unpack2(acc2[i][0], c[0], c[1]);
        unpack2(acc2[i][1], c[2], c[3]);
#pragma unroll
        for (int j = 0; j < 4; j++) {
            int n = bn + tx * 4 + j;
            if (n >= N) continue;
            float v = c[j];
            float gg = gv ? gv[n] : 1.f;
            float bb = bv ? bv[n] : 0.f;
            v = __fadd_rn(__fmul_rn(v, gg), bb);
            if (EPI == EPI_AFF_LRELU)
                v = (v >= 0.f) ? v : __fmul_rn(0.2f, v);
            C[(size_t)m * ldc + n] = v;
        }
    }
}

// ---------------- helpers ---------------------------------------------------
__global__ void concat_kernel(const float* __restrict__ pts,
                              const float* __restrict__ feat,
                              float* __restrict__ X0,
                              float* __restrict__ Xt, int N)
{
    int n = blockIdx.x * blockDim.x + threadIdx.x;
    if (n >= N) return;
    float x = pts[n * 3 + 0];
    float y = pts[n * 3 + 1];
    float z = pts[n * 3 + 2];
    float f = feat[n];
    X0[n * 4 + 0] = x;
    X0[n * 4 + 1] = y;
    X0[n * 4 + 2] = z;
    X0[n * 4 + 3] = f;
    Xt[(size_t)0 * N + n] = x;
    Xt[(size_t)1 * N + n] = y;
    Xt[(size_t)2 * N + n] = z;
    Xt[(size_t)3 * N + n] = f;
}

// ---------------- fused edge conv (exact fp32) + transposed output ---------
template <int C>
__global__ void __launch_bounds__(256) edge_conv_kernel(
    const float* __restrict__ X, int lda,
    const float* __restrict__ w,      // [64, 2C]
    const int* __restrict__ idx,
    const float* __restrict__ g, const float* __restrict__ b,
    float* __restrict__ out, int colofs,
    float* __restrict__ Xt, int N)
{
    __shared__ float ws[2 * C][64];
    __shared__ float xs[4][C];
    __shared__ float ds[4][C];

    int tid = threadIdx.x;
    int o = tid & 63;
    int r = tid >> 6;
    int n = blockIdx.x * 4 + r;
    bool active = (n < N);

    for (int e = tid; e < 2 * C * 64; e += 256) {
        int oo = e / (2 * C), cc = e % (2 * C);
        ws[cc][oo] = w[oo * 2 * C + cc];
    }
    if (active) {
        for (int c = o; c < C; c += 64)
            xs[r][c] = X[(size_t)n * lda + c];
    }
    __syncthreads();

    float gg = active ? g[o] : 0.f;
    float bb = active ? b[o] : 0.f;
    float m = -FLT_MAX;
    const int* row = idx + (size_t)(active ? n : 0) * KNN;

    for (int k = 0; k < KNN; k++) {
        int j = active ? row[k] : 0;
        if (active && o < C)
            ds[r][o] = __fsub_rn(X[(size_t)j * lda + o], xs[r][o]);
        __syncthreads();
        if (active) {
            float y = 0.f;
#pragma unroll
            for (int c = 0; c < C; c++)
                y = fmaf(ds[r][c], ws[c][o], y);
#pragma unroll
            for (int c = 0; c < C; c++)
                y = fmaf(xs[r][c], ws[C + c][o], y);
            float z = __fadd_rn(__fmul_rn(y, gg), bb);
            z = (z >= 0.f) ? z : __fmul_rn(0.2f, z);
            m = fmaxf(m, z);
        }
        __syncthreads();
    }
    if (active) {
        out[(size_t)n * 256 + colofs + o] = m;
        if (Xt) Xt[(size_t)o * N + n] = m;
    }
}

// ---------------- launch ----------------------------------------------------
static inline int fused_smem_bytes(int KD) {
    return KD * 68 * 4 + KD * 132 * 4 + 64 * KNN * 4 * 2
         + 64 * CAPB * 4 * 2 + 5 * 64 * 4;
}

extern "C" void kernel_launch(void* const* d_in, const int* in_sizes, int n_in,
                              void* d_out, int out_size)
{
    const float* pts   = (const float*)d_in[0];
    const float* feats = (const float*)d_in[1];
    const float* W[4]  = { (const float*)d_in[2], (const float*)d_in[5],
                           (const float*)d_in[8], (const float*)d_in[11] };
    const float* G[4]  = { (const float*)d_in[3], (const float*)d_in[6],
                           (const float*)d_in[9], (const float*)d_in[12] };
    const float* Bv[4] = { (const float*)d_in[4], (const float*)d_in[7],
                           (const float*)d_in[10], (const float*)d_in[13] };
    const float* w5 = (const float*)d_in[14];
    const float* g5 = (const float*)d_in[15];
    const float* b5 = (const float*)d_in[16];
    const float* wf = (const float*)d_in[17];
    const float* go = (const float*)d_in[18];
    const float* bo = (const float*)d_in[19];
    const float* wh = (const float*)d_in[20];
    const float* bh = (const float*)d_in[21];
    float* outp = (float*)d_out;

    int N = in_sizes[0] / 3;   // 12000

    float *pX0, *pXt, *pX14, *pY5, *pF, *ppd;
    int *pidx, *ppi;
    cudaGetSymbolAddress((void**)&pidx, g_idx);
    cudaGetSymbolAddress((void**)&ppd,  g_pd);
    cudaGetSymbolAddress((void**)&ppi,  g_pi);
    cudaGetSymbolAddress((void**)&pX0,  g_X0);
    cudaGetSymbolAddress((void**)&pXt,  g_Xt);
    cudaGetSymbolAddress((void**)&pX14, g_X14);
    cudaGetSymbolAddress((void**)&pY5,  g_Y5);
    cudaGetSymbolAddress((void**)&pF,   g_F);

    static bool attr_done = false;
    if (!attr_done) {
        cudaFuncSetAttribute(fused_knn<4>,
            cudaFuncAttributeMaxDynamicSharedMemorySize, fused_smem_bytes(4));
        cudaFuncSetAttribute(fused_knn<64>,
            cudaFuncAttributeMaxDynamicSharedMemorySize, fused_smem_bytes(64));
        attr_done = true;
    }

    int nb256 = (N + 255) / 256;
    int nb4   = (N + 3) / 4;
    int nbM   = (N + FTM - 1) / FTM;
    dim3 gKnn(nbM, NCHUNK);

    // L1
    concat_kernel<<<nb256, 256>>>(pts, feats, pX0, pXt, N);
    fused_knn<4><<<gKnn, 256, fused_smem_bytes(4)>>>(pXt, ppd, ppi, N);
    knn_merge_kernel<<<nb256, 256>>>(ppd, ppi, pidx, N);
    edge_conv_kernel<4><<<nb4, 256>>>(pX0, 4, W[0], pidx, G[0], Bv[0],
                                      pX14, 0, pXt, N);

    // L2..L4
    for (int blk = 1; blk < 4; blk++) {
        const float* Xin = pX14 + (blk - 1) * 64;
        fused_knn<64><<<gKnn, 256, fused_smem_bytes(64)>>>(pXt, ppd, ppi, N);
        knn_merge_kernel<<<nb256, 256>>>(ppd, ppi, pidx, N);
        edge_conv_kernel<64><<<nb4, 256>>>(Xin, 256, W[blk], pidx,
                                           G[blk], Bv[blk], pX14, blk * 64,
                                           (blk < 3) ? pXt : nullptr, N);
    }

    // conv5 / feat / head
    sgemm_nt<EPI_AFF_LRELU><<<dim3((1024 + 63) / 64, (N + 63) / 64), 256>>>(
        pX14, 256, w5, 256, pY5, 1024, N, 1024, 256, g5, b5);
    sgemm_nt<EPI_AFF><<<dim3((256 + 63) / 64, (N + 63) / 64), 256>>>(
        pY5, 1024, wf, 1024, pF, 256, N, 256, 1024, go, bo);
    sgemm_nt<EPI_AFF><<<dim3(1, (N + 63) / 64), 256>>>(
        pF, 256, wh, 256, outp, 20, N, 20, 256, nullptr, bh);
}